// round 15
// baseline (speedup 1.0000x reference)
#include <cuda_runtime.h>
#include <cuda_bf16.h>
#include <cstdint>

#define NCTA 128
#define THR  512

// word-offsets in dynamic smem
#define W_X    0          // GEMM1 X f32: 2 bufs x (128 rows x 72 words)
#define XBUF   9216
#define W_DW   18432      // GEMM1 dw bf16: 2 bufs x (hi 64x36 + lo 64x36)
#define DWBUF  4608
#define W_U    0          // GEMM2 uw bf16: 3 bufs x (hi 128x36 + lo 128x36), reuses region
#define UBUF   9216
#define W_DSM  27648      // 128 x 66 f32
#define W_RH   36096      // R hi: 128 rows x 36 words (shorts stride 72)
#define W_RL   40704
#define SMEM_SZ (45312*4)

__device__ unsigned short g_dwh[64*4096], g_dwl[64*4096];
__device__ unsigned short g_uwh[4096*64], g_uwl[4096*64];

static __device__ __forceinline__ uint32_t pk2(float lo, float hi) {
    uint32_t r; asm("cvt.rn.bf16x2.f32 %0, %1, %2;" : "=r"(r) : "f"(hi), "f"(lo)); return r;
}
static __device__ __forceinline__ void bmma(float d[4], const uint32_t a[4],
                                            uint32_t b0, uint32_t b1) {
    asm("mma.sync.aligned.m16n8k16.row.col.f32.bf16.bf16.f32 "
        "{%0,%1,%2,%3},{%4,%5,%6,%7},{%8,%9},{%0,%1,%2,%3};"
        : "+f"(d[0]), "+f"(d[1]), "+f"(d[2]), "+f"(d[3])
        : "r"(a[0]), "r"(a[1]), "r"(a[2]), "r"(a[3]), "r"(b0), "r"(b1));
}
static __device__ __forceinline__ uint32_t smem_u32(const void* p) {
    uint32_t a;
    asm("{ .reg .u64 t; cvta.to.shared.u64 t, %1; cvt.u32.u64 %0, t; }" : "=r"(a) : "l"(p));
    return a;
}
static __device__ __forceinline__ void cpa(uint32_t s, const void* g) {
    asm volatile("cp.async.ca.shared.global [%0], [%1], 16;" :: "r"(s), "l"(g) : "memory");
}
#define CPC()  asm volatile("cp.async.commit_group;" ::: "memory")
#define CPW0() asm volatile("cp.async.wait_group 0;" ::: "memory")
#define CPW1() asm volatile("cp.async.wait_group 1;" ::: "memory")

__global__ void kprep(const float* __restrict__ dw, const float* __restrict__ uw) {
    int i = blockIdx.x * 256 + threadIdx.x;
    float v = (i < 262144) ? dw[i] : uw[i - 262144];
    __nv_bfloat16 hb = __float2bfloat16(v);
    float l = v - __bfloat162float(hb);
    __nv_bfloat16 lb = __float2bfloat16(l);
    unsigned short hu = *(unsigned short*)&hb, lu = *(unsigned short*)&lb;
    if (i < 262144) { g_dwh[i] = hu; g_dwl[i] = lu; }
    else            { g_uwh[i - 262144] = hu; g_uwl[i - 262144] = lu; }
}

__global__ __launch_bounds__(THR, 1) void moe_mma(
    const float* __restrict__ x, const float* __restrict__ tv,
    const long long* __restrict__ ti, float* __restrict__ out)
{
    extern __shared__ uint32_t sm[];
    float* smf = (float*)sm;
    const uint32_t su = smem_u32(sm);
    const int tid = threadIdx.x, wid = tid >> 5, lane = tid & 31;
    const int lr = lane >> 2, lc = lane & 3;
    const int kh = wid >> 3;                       // GEMM1 k-half (0/1)
    const int team = wid & 7, tm = team >> 1, tn = team & 1;   // m32 x n32 team tile
    const int wm = wid >> 2, wn = wid & 3;         // GEMM2 mapping
    const int row0 = blockIdx.x * 128;

    const float4* x4 = (const float4*)x;

    // ---- prologue: stage GEMM1 chunk 0 ----
    {
        uint32_t xb = su + W_X * 4;
        #pragma unroll
        for (int j = 0; j < 4; j++) {
            int f = tid + j * THR, r = f >> 4, q = f & 15;
            cpa(xb + (r*72 + q*4)*4, x4 + (size_t)(row0 + r)*1024 + q);
        }
        uint32_t db = su + W_DW * 4;
        #pragma unroll
        for (int j = 0; j < 2; j++) {
            int f = tid + j * THR, hf = f >> 9, g = f & 511, n = g >> 3, q = g & 7;
            const unsigned short* src = (hf ? g_dwl : g_dwh) + n*4096 + q*8;
            cpa(db + (hf*2304 + n*36 + q*4)*4, src);
        }
        CPC();
    }

    // ---- pack top-k indices (int32/int64 auto-detect, in-bounds) ----
    uint32_t plo = 0, phi = 0;
    {
        const int* t32b = (const int*)ti;
        bool is64 = ((t32b[1]|t32b[3]|t32b[5]|t32b[7]|t32b[9]|t32b[11]|t32b[13]|t32b[15]) == 0);
        if (tid < 128) {
            int row = row0 + tid;
            if (is64) {
                const long long* t = ti + (size_t)row * 8;
                #pragma unroll
                for (int k = 0; k < 4; k++) { plo |= ((uint32_t)t[k]&63u)<<(8*k); phi |= ((uint32_t)t[4+k]&63u)<<(8*k); }
            } else {
                const int* t = t32b + (size_t)row * 8;
                #pragma unroll
                for (int k = 0; k < 4; k++) { plo |= ((uint32_t)t[k]&63u)<<(8*k); phi |= ((uint32_t)t[4+k]&63u)<<(8*k); }
            }
        }
    }
    // zero R region (9216 words)
    #pragma unroll
    for (int j = 0; j < 18; j++) sm[W_RH + tid + j*THR] = 0;

    // ===== GEMM1: D1[128,64] = X_tile @ dw^T, 64 chunks x 64 cols, split-K x2 =====
    float acc[2][4][4];
    #pragma unroll
    for (int i = 0; i < 2; i++)
        #pragma unroll
        for (int nt = 0; nt < 4; nt++) { acc[i][nt][0]=acc[i][nt][1]=acc[i][nt][2]=acc[i][nt][3]=0.f; }

    #pragma unroll 1
    for (int c = 0; c < 64; c++) {
        CPW0();            // my copies of chunk c complete (pending = {c})
        __syncthreads();   // ALL threads' chunk-c copies visible; compute c-1 retired
        if (c < 63) {      // stage chunk c+1 (rides behind compute of c)
            uint32_t xb = su + (W_X + ((c+1)&1)*XBUF) * 4;
            #pragma unroll
            for (int j = 0; j < 4; j++) {
                int f = tid + j * THR, r = f >> 4, q = f & 15;
                cpa(xb + (r*72 + q*4)*4, x4 + (size_t)(row0 + r)*1024 + (c+1)*16 + q);
            }
            uint32_t db = su + (W_DW + ((c+1)&1)*DWBUF) * 4;
            #pragma unroll
            for (int j = 0; j < 2; j++) {
                int f = tid + j * THR, hf = f >> 9, g = f & 511, n = g >> 3, q = g & 7;
                const unsigned short* src = (hf ? g_dwl : g_dwh) + n*4096 + (c+1)*64 + q*8;
                cpa(db + (hf*2304 + n*36 + q*4)*4, src);
            }
            CPC();
        }

        if (kh == (c & 1)) {
            const uint32_t xw = W_X + (c&1)*XBUF;
            const uint32_t bh = W_DW + (c&1)*DWBUF;
            const uint32_t bl = bh + 2304;
            #pragma unroll
            for (int s = 0; s < 4; s++) {
                uint32_t B0h[4], B1h[4], B0l[4], B1l[4];
                #pragma unroll
                for (int nt = 0; nt < 4; nt++) {
                    uint32_t wb = ((tn*4+nt)*8 + lr)*36 + s*8 + lc;
                    B0h[nt] = sm[bh+wb]; B1h[nt] = sm[bh+wb+4];
                    B0l[nt] = sm[bl+wb]; B1l[nt] = sm[bl+wb+4];
                }
                uint32_t ah[2][4], al[2][4];
                #pragma unroll
                for (int i = 0; i < 2; i++)
                    #pragma unroll
                    for (int j = 0; j < 4; j++) {
                        int r  = tm*32 + i*16 + lr + (j & 1)*8;
                        int ko = s*16 + lc*2 + (j >> 1)*8;
                        float2 f = *(float2*)&smf[xw + r*72 + ko];
                        uint32_t hh = pk2(f.x, f.y);
                        float lx = f.x - __uint_as_float(hh << 16);
                        float ly = f.y - __uint_as_float(hh & 0xffff0000u);
                        ah[i][j] = hh; al[i][j] = pk2(lx, ly);
                    }
                #pragma unroll
                for (int i = 0; i < 2; i++)
                    #pragma unroll
                    for (int nt = 0; nt < 4; nt++) bmma(acc[i][nt], ah[i], B0h[nt], B1h[nt]);
                #pragma unroll
                for (int i = 0; i < 2; i++)
                    #pragma unroll
                    for (int nt = 0; nt < 4; nt++) bmma(acc[i][nt], ah[i], B0l[nt], B1l[nt]);
                #pragma unroll
                for (int i = 0; i < 2; i++)
                    #pragma unroll
                    for (int nt = 0; nt < 4; nt++) bmma(acc[i][nt], al[i], B0h[nt], B1h[nt]);
            }
        }
    }

    // ---- transition: stage GEMM2 chunks 0,1 (hides DRAM behind reduce/gather) ----
    __syncthreads();   // chunk-63 compute done everywhere; staging region free
    #pragma unroll
    for (int cc = 0; cc < 2; cc++) {
        uint32_t ub = su + (W_U + cc * UBUF) * 4;
        #pragma unroll
        for (int j = 0; j < 4; j++) {
            int f = tid + j * THR, hf = f >> 10, g = f & 1023, n = g >> 3, q = g & 7;
            const unsigned short* src = (hf ? g_uwl : g_uwh) + (size_t)(cc*128 + n)*64 + q*8;
            cpa(ub + (hf*4608 + n*36 + q*4)*4, src);
        }
        CPC();
    }

    // ---- reduce 2 k-halves into Dsm ----
    if (kh == 0) {
        #pragma unroll
        for (int i = 0; i < 2; i++)
            #pragma unroll
            for (int nt = 0; nt < 4; nt++) {
                uint32_t wd = W_DSM + (tm*32 + i*16 + lr)*66 + tn*32 + nt*8 + lc*2;
                *(float2*)&sm[wd]       = make_float2(acc[i][nt][0], acc[i][nt][1]);
                *(float2*)&sm[wd + 528] = make_float2(acc[i][nt][2], acc[i][nt][3]);
            }
    }
    __syncthreads();
    if (kh == 1) {
        #pragma unroll
        for (int i = 0; i < 2; i++)
            #pragma unroll
            for (int nt = 0; nt < 4; nt++) {
                uint32_t wd = W_DSM + (tm*32 + i*16 + lr)*66 + tn*32 + nt*8 + lc*2;
                float2 u0 = *(float2*)&sm[wd], u1 = *(float2*)&sm[wd + 528];
                u0.x += acc[i][nt][0]; u0.y += acc[i][nt][1];
                u1.x += acc[i][nt][2]; u1.y += acc[i][nt][3];
                *(float2*)&sm[wd]       = u0;
                *(float2*)&sm[wd + 528] = u1;
            }
    }
    __syncthreads();

    // ---- gather * scale -> sparse R (bf16 split) ----
    if (tid < 128) {
        const float* tvr = tv + (size_t)(row0 + tid)*8;
        #pragma unroll
        for (int k = 0; k < 8; k++) {
            uint32_t idx = ((k < 4 ? plo : phi) >> (8*(k&3))) & 63u;
            float v = smf[W_DSM + tid*66 + idx] * tvr[k];
            __nv_bfloat16 hb = __float2bfloat16(v);
            float l = v - __bfloat162float(hb);
            __nv_bfloat16 lb = __float2bfloat16(l);
            ((unsigned short*)&sm[W_RH])[tid*72 + idx] = *(unsigned short*)&hb;
            ((unsigned short*)&sm[W_RL])[tid*72 + idx] = *(unsigned short*)&lb;
        }
    }

    // ===== GEMM2: out[128,4096] = R @ uw^T, 32 chunks x 128 cols, 8 indep accs =====
    float d[4][2][4];
    #pragma unroll
    for (int tt = 0; tt < 4; tt++)
        #pragma unroll
        for (int i = 0; i < 2; i++) { d[tt][i][0]=d[tt][i][1]=d[tt][i][2]=d[tt][i][3]=0.f; }

    #pragma unroll 1
    for (int ch = 0; ch < 32; ch++) {
        if (ch < 31) CPW1(); else CPW0();   // my copies of chunk ch complete
        __syncthreads();                    // all threads' copies visible; compute ch-1 retired; R ready (ch=0)
        if (ch + 2 < 32) {                  // stage ch+2 (rides behind compute of ch)
            uint32_t ub = su + (W_U + ((ch + 2) % 3) * UBUF) * 4;
            #pragma unroll
            for (int j = 0; j < 4; j++) {
                int f = tid + j * THR, hf = f >> 10, g = f & 1023, n = g >> 3, q = g & 7;
                const unsigned short* src = (hf ? g_uwl : g_uwh) + (size_t)((ch+2)*128 + n)*64 + q*8;
                cpa(ub + (hf*4608 + n*36 + q*4)*4, src);
            }
            CPC();
        }

        const uint32_t uh = W_U + (ch % 3) * UBUF;
        const uint32_t ul = uh + 4608;
        #pragma unroll
        for (int s = 0; s < 4; s++) {
            uint32_t Ah[2][4], Al[2][4];
            #pragma unroll
            for (int i = 0; i < 2; i++) {
                uint32_t wa = ((wm*2+i)*16 + lr)*36 + s*8 + lc;
                Ah[i][0] = sm[W_RH+wa]; Ah[i][1] = sm[W_RH+wa+288]; Ah[i][2] = sm[W_RH+wa+4]; Ah[i][3] = sm[W_RH+wa+292];
                Al[i][0] = sm[W_RL+wa]; Al[i][1] = sm[W_RL+wa+288]; Al[i][2] = sm[W_RL+wa+4]; Al[i][3] = sm[W_RL+wa+292];
            }
            uint32_t B0h[4], B1h[4], B0l[4], B1l[4];
            #pragma unroll
            for (int tt = 0; tt < 4; tt++) {
                uint32_t wb = ((wn*4+tt)*8 + lr)*36 + s*8 + lc;
                B0h[tt] = sm[uh+wb]; B1h[tt] = sm[uh+wb+4];
                B0l[tt] = sm[ul+wb]; B1l[tt] = sm[ul+wb+4];
            }
            #pragma unroll
            for (int tt = 0; tt < 4; tt++)
                #pragma unroll
                for (int i = 0; i < 2; i++) bmma(d[tt][i], Ah[i], B0h[tt], B1h[tt]);
            #pragma unroll
            for (int tt = 0; tt < 4; tt++)
                #pragma unroll
                for (int i = 0; i < 2; i++) bmma(d[tt][i], Ah[i], B0l[tt], B1l[tt]);
            #pragma unroll
            for (int tt = 0; tt < 4; tt++)
                #pragma unroll
                for (int i = 0; i < 2; i++) bmma(d[tt][i], Al[i], B0h[tt], B1h[tt]);
        }
        // store + reset accumulators
        #pragma unroll
        for (int tt = 0; tt < 4; tt++)
            #pragma unroll
            for (int i = 0; i < 2; i++) {
                size_t o = (size_t)(row0 + (wm*2+i)*16 + lr)*4096 + ch*128 + (wn*4+tt)*8 + lc*2;
                *(float2*)&out[o]          = make_float2(d[tt][i][0], d[tt][i][1]);
                *(float2*)&out[o + 8*4096] = make_float2(d[tt][i][2], d[tt][i][3]);
                d[tt][i][0]=d[tt][i][1]=d[tt][i][2]=d[tt][i][3]=0.f;
            }
    }
}

extern "C" void kernel_launch(void* const* d_in, const int* in_sizes, int n_in,
                              void* d_out, int out_size)
{
    const float*     x  = (const float*)d_in[0];      // [16384,4096]
    const float*     dw = (const float*)d_in[1];      // [64,4096]
    const float*     uw = (const float*)d_in[2];      // [4096,64]
    const float*     tv = (const float*)d_in[3];      // [16384,8]
    const long long* ti = (const long long*)d_in[4];  // [16384,8] i32/i64

    cudaFuncSetAttribute(moe_mma, cudaFuncAttributeMaxDynamicSharedMemorySize, SMEM_SZ);
    kprep<<<2048, 256>>>(dw, uw);
    moe_mma<<<NCTA, THR, SMEM_SZ>>>(x, tv, ti, (float*)d_out);
}

// round 16
// speedup vs baseline: 1.1954x; 1.1954x over previous
#include <cuda_runtime.h>
#include <cuda_bf16.h>
#include <cstdint>

#define NCTA 128
#define THR  512

// word-offsets in dynamic smem
#define W_X    0          // GEMM1 X f32: 3 bufs x (128 rows x 72 words)
#define XBUF   9216
#define W_DW   27648      // GEMM1 dw bf16: 3 bufs x (hi 64x36 + lo 64x36)
#define DWBUF  4608
#define W_U    0          // GEMM2 uw bf16: 3 bufs x (hi 128x36 + lo 128x36), reuses X region
#define UBUF   9216
#define W_DSM  27648      // 128 x 66 f32 (reuses DW region after GEMM1)
#define W_RH   41472      // R hi: 128 rows x 36 words (shorts stride 72)
#define W_RL   46080
#define SMEM_SZ (50688*4)

__device__ unsigned short g_dwh[64*4096], g_dwl[64*4096];
__device__ unsigned short g_uwh[4096*64], g_uwl[4096*64];

static __device__ __forceinline__ uint32_t pk2(float lo, float hi) {
    uint32_t r; asm("cvt.rn.bf16x2.f32 %0, %1, %2;" : "=r"(r) : "f"(hi), "f"(lo)); return r;
}
static __device__ __forceinline__ void bmma(float d[4], const uint32_t a[4],
                                            uint32_t b0, uint32_t b1) {
    asm("mma.sync.aligned.m16n8k16.row.col.f32.bf16.bf16.f32 "
        "{%0,%1,%2,%3},{%4,%5,%6,%7},{%8,%9},{%0,%1,%2,%3};"
        : "+f"(d[0]), "+f"(d[1]), "+f"(d[2]), "+f"(d[3])
        : "r"(a[0]), "r"(a[1]), "r"(a[2]), "r"(a[3]), "r"(b0), "r"(b1));
}
static __device__ __forceinline__ uint32_t smem_u32(const void* p) {
    uint32_t a;
    asm("{ .reg .u64 t; cvta.to.shared.u64 t, %1; cvt.u32.u64 %0, t; }" : "=r"(a) : "l"(p));
    return a;
}
static __device__ __forceinline__ void cpa(uint32_t s, const void* g) {
    asm volatile("cp.async.ca.shared.global [%0], [%1], 16;" :: "r"(s), "l"(g) : "memory");
}
#define CPC()  asm volatile("cp.async.commit_group;" ::: "memory")
#define CPW0() asm volatile("cp.async.wait_group 0;" ::: "memory")
#define CPW1() asm volatile("cp.async.wait_group 1;" ::: "memory")

__global__ void kprep(const float* __restrict__ dw, const float* __restrict__ uw) {
    int i = blockIdx.x * 256 + threadIdx.x;
    float v = (i < 262144) ? dw[i] : uw[i - 262144];
    __nv_bfloat16 hb = __float2bfloat16(v);
    float l = v - __bfloat162float(hb);
    __nv_bfloat16 lb = __float2bfloat16(l);
    unsigned short hu = *(unsigned short*)&hb, lu = *(unsigned short*)&lb;
    if (i < 262144) { g_dwh[i] = hu; g_dwl[i] = lu; }
    else            { g_uwh[i - 262144] = hu; g_uwl[i - 262144] = lu; }
}

__global__ __launch_bounds__(THR, 1) void moe_mma(
    const float* __restrict__ x, const float* __restrict__ tv,
    const long long* __restrict__ ti, float* __restrict__ out)
{
    extern __shared__ uint32_t sm[];
    float* smf = (float*)sm;
    const uint32_t su = smem_u32(sm);
    const int tid = threadIdx.x, wid = tid >> 5, lane = tid & 31;
    const int lr = lane >> 2, lc = lane & 3;
    const int kh = wid >> 3;                       // GEMM1 k-half (0/1)
    const int team = wid & 7, tm = team >> 1, tn = team & 1;   // m32 x n32 team tile
    const int wm = wid >> 2, wn = wid & 3;         // GEMM2 mapping
    const int row0 = blockIdx.x * 128;

    const float4* x4 = (const float4*)x;

    // ---- prologue: stage GEMM1 chunks 0 and 1 (2 groups in flight) ----
    #pragma unroll
    for (int cc = 0; cc < 2; cc++) {
        uint32_t xb = su + (W_X + cc * XBUF) * 4;
        #pragma unroll
        for (int j = 0; j < 4; j++) {
            int f = tid + j * THR, r = f >> 4, q = f & 15;
            cpa(xb + (r*72 + q*4)*4, x4 + (size_t)(row0 + r)*1024 + cc*16 + q);
        }
        uint32_t db = su + (W_DW + cc * DWBUF) * 4;
        #pragma unroll
        for (int j = 0; j < 2; j++) {
            int f = tid + j * THR, hf = f >> 9, g = f & 511, n = g >> 3, q = g & 7;
            const unsigned short* src = (hf ? g_dwl : g_dwh) + n*4096 + cc*64 + q*8;
            cpa(db + (hf*2304 + n*36 + q*4)*4, src);
        }
        CPC();
    }

    // ---- pack top-k indices (int32/int64 auto-detect, in-bounds) ----
    uint32_t plo = 0, phi = 0;
    {
        const int* t32b = (const int*)ti;
        bool is64 = ((t32b[1]|t32b[3]|t32b[5]|t32b[7]|t32b[9]|t32b[11]|t32b[13]|t32b[15]) == 0);
        if (tid < 128) {
            int row = row0 + tid;
            if (is64) {
                const long long* t = ti + (size_t)row * 8;
                #pragma unroll
                for (int k = 0; k < 4; k++) { plo |= ((uint32_t)t[k]&63u)<<(8*k); phi |= ((uint32_t)t[4+k]&63u)<<(8*k); }
            } else {
                const int* t = t32b + (size_t)row * 8;
                #pragma unroll
                for (int k = 0; k < 4; k++) { plo |= ((uint32_t)t[k]&63u)<<(8*k); phi |= ((uint32_t)t[4+k]&63u)<<(8*k); }
            }
        }
    }
    // zero R region (9216 words)
    #pragma unroll
    for (int j = 0; j < 18; j++) sm[W_RH + tid + j*THR] = 0;

    // ===== GEMM1: D1[128,64] = X_tile @ dw^T, 64 chunks x 64 cols, split-K x2 =====
    float acc[2][4][4];
    #pragma unroll
    for (int i = 0; i < 2; i++)
        #pragma unroll
        for (int nt = 0; nt < 4; nt++) { acc[i][nt][0]=acc[i][nt][1]=acc[i][nt][2]=acc[i][nt][3]=0.f; }

    #pragma unroll 1
    for (int c = 0; c < 64; c++) {
        if (c < 63) CPW1(); else CPW0();    // my copies of chunk c complete (c+1 may fly)
        __syncthreads();                    // all threads' chunk-c copies visible; compute c-1 retired
        if (c + 2 < 64) {                   // stage chunk c+2 (rides behind compute of c)
            int b2 = (c + 2) % 3;
            uint32_t xb = su + (W_X + b2 * XBUF) * 4;
            #pragma unroll
            for (int j = 0; j < 4; j++) {
                int f = tid + j * THR, r = f >> 4, q = f & 15;
                cpa(xb + (r*72 + q*4)*4, x4 + (size_t)(row0 + r)*1024 + (c+2)*16 + q);
            }
            uint32_t db = su + (W_DW + b2 * DWBUF) * 4;
            #pragma unroll
            for (int j = 0; j < 2; j++) {
                int f = tid + j * THR, hf = f >> 9, g = f & 511, n = g >> 3, q = g & 7;
                const unsigned short* src = (hf ? g_dwl : g_dwh) + n*4096 + (c+2)*64 + q*8;
                cpa(db + (hf*2304 + n*36 + q*4)*4, src);
            }
            CPC();
        }

        if (kh == (c & 1)) {
            const int bp = c % 3;
            const uint32_t xw = W_X + bp * XBUF;
            const uint32_t bh = W_DW + bp * DWBUF;
            const uint32_t bl = bh + 2304;
            #pragma unroll
            for (int s = 0; s < 4; s++) {
                uint32_t B0h[4], B1h[4], B0l[4], B1l[4];
                #pragma unroll
                for (int nt = 0; nt < 4; nt++) {
                    uint32_t wb = ((tn*4+nt)*8 + lr)*36 + s*8 + lc;
                    B0h[nt] = sm[bh+wb]; B1h[nt] = sm[bh+wb+4];
                    B0l[nt] = sm[bl+wb]; B1l[nt] = sm[bl+wb+4];
                }
                uint32_t ah[2][4], al[2][4];
                #pragma unroll
                for (int i = 0; i < 2; i++)
                    #pragma unroll
                    for (int j = 0; j < 4; j++) {
                        int r  = tm*32 + i*16 + lr + (j & 1)*8;
                        int ko = s*16 + lc*2 + (j >> 1)*8;
                        float2 f = *(float2*)&smf[xw + r*72 + ko];
                        uint32_t hh = pk2(f.x, f.y);
                        float lx = f.x - __uint_as_float(hh << 16);
                        float ly = f.y - __uint_as_float(hh & 0xffff0000u);
                        ah[i][j] = hh; al[i][j] = pk2(lx, ly);
                    }
                #pragma unroll
                for (int i = 0; i < 2; i++)
                    #pragma unroll
                    for (int nt = 0; nt < 4; nt++) bmma(acc[i][nt], ah[i], B0h[nt], B1h[nt]);
                #pragma unroll
                for (int i = 0; i < 2; i++)
                    #pragma unroll
                    for (int nt = 0; nt < 4; nt++) bmma(acc[i][nt], ah[i], B0l[nt], B1l[nt]);
                #pragma unroll
                for (int i = 0; i < 2; i++)
                    #pragma unroll
                    for (int nt = 0; nt < 4; nt++) bmma(acc[i][nt], al[i], B0h[nt], B1h[nt]);
            }
        }
    }

    // ---- transition: stage GEMM2 chunks 0,1 (hides DRAM behind reduce/gather) ----
    __syncthreads();   // chunk-63 compute done everywhere; X region free
    #pragma unroll
    for (int cc = 0; cc < 2; cc++) {
        uint32_t ub = su + (W_U + cc * UBUF) * 4;
        #pragma unroll
        for (int j = 0; j < 4; j++) {
            int f = tid + j * THR, hf = f >> 10, g = f & 1023, n = g >> 3, q = g & 7;
            const unsigned short* src = (hf ? g_uwl : g_uwh) + (size_t)(cc*128 + n)*64 + q*8;
            cpa(ub + (hf*4608 + n*36 + q*4)*4, src);
        }
        CPC();
    }

    // ---- reduce 2 k-halves into Dsm (reuses DW region) ----
    if (kh == 0) {
        #pragma unroll
        for (int i = 0; i < 2; i++)
            #pragma unroll
            for (int nt = 0; nt < 4; nt++) {
                uint32_t wd = W_DSM + (tm*32 + i*16 + lr)*66 + tn*32 + nt*8 + lc*2;
                *(float2*)&sm[wd]       = make_float2(acc[i][nt][0], acc[i][nt][1]);
                *(float2*)&sm[wd + 528] = make_float2(acc[i][nt][2], acc[i][nt][3]);
            }
    }
    __syncthreads();
    if (kh == 1) {
        #pragma unroll
        for (int i = 0; i < 2; i++)
            #pragma unroll
            for (int nt = 0; nt < 4; nt++) {
                uint32_t wd = W_DSM + (tm*32 + i*16 + lr)*66 + tn*32 + nt*8 + lc*2;
                float2 u0 = *(float2*)&sm[wd], u1 = *(float2*)&sm[wd + 528];
                u0.x += acc[i][nt][0]; u0.y += acc[i][nt][1];
                u1.x += acc[i][nt][2]; u1.y += acc[i][nt][3];
                *(float2*)&sm[wd]       = u0;
                *(float2*)&sm[wd + 528] = u1;
            }
    }
    __syncthreads();

    // ---- gather * scale -> sparse R (bf16 split) ----
    if (tid < 128) {
        const float* tvr = tv + (size_t)(row0 + tid)*8;
        #pragma unroll
        for (int k = 0; k < 8; k++) {
            uint32_t idx = ((k < 4 ? plo : phi) >> (8*(k&3))) & 63u;
            float v = smf[W_DSM + tid*66 + idx] * tvr[k];
            __nv_bfloat16 hb = __float2bfloat16(v);
            float l = v - __bfloat162float(hb);
            __nv_bfloat16 lb = __float2bfloat16(l);
            ((unsigned short*)&sm[W_RH])[tid*72 + idx] = *(unsigned short*)&hb;
            ((unsigned short*)&sm[W_RL])[tid*72 + idx] = *(unsigned short*)&lb;
        }
    }

    // ===== GEMM2: out[128,4096] = R @ uw^T, 32 chunks x 128 cols, 8 indep accs =====
    float d[4][2][4];
    #pragma unroll
    for (int tt = 0; tt < 4; tt++)
        #pragma unroll
        for (int i = 0; i < 2; i++) { d[tt][i][0]=d[tt][i][1]=d[tt][i][2]=d[tt][i][3]=0.f; }

    #pragma unroll 1
    for (int ch = 0; ch < 32; ch++) {
        if (ch < 31) CPW1(); else CPW0();   // my copies of chunk ch complete
        __syncthreads();                    // all copies visible; compute ch-1 retired; R ready (ch=0)
        if (ch + 2 < 32) {                  // stage ch+2 (rides behind compute of ch)
            uint32_t ub = su + (W_U + ((ch + 2) % 3) * UBUF) * 4;
            #pragma unroll
            for (int j = 0; j < 4; j++) {
                int f = tid + j * THR, hf = f >> 10, g = f & 1023, n = g >> 3, q = g & 7;
                const unsigned short* src = (hf ? g_uwl : g_uwh) + (size_t)((ch+2)*128 + n)*64 + q*8;
                cpa(ub + (hf*4608 + n*36 + q*4)*4, src);
            }
            CPC();
        }

        const uint32_t uh = W_U + (ch % 3) * UBUF;
        const uint32_t ul = uh + 4608;
        #pragma unroll
        for (int s = 0; s < 4; s++) {
            uint32_t Ah[2][4], Al[2][4];
            #pragma unroll
            for (int i = 0; i < 2; i++) {
                uint32_t wa = ((wm*2+i)*16 + lr)*36 + s*8 + lc;
                Ah[i][0] = sm[W_RH+wa]; Ah[i][1] = sm[W_RH+wa+288]; Ah[i][2] = sm[W_RH+wa+4]; Ah[i][3] = sm[W_RH+wa+292];
                Al[i][0] = sm[W_RL+wa]; Al[i][1] = sm[W_RL+wa+288]; Al[i][2] = sm[W_RL+wa+4]; Al[i][3] = sm[W_RL+wa+292];
            }
            uint32_t B0h[4], B1h[4], B0l[4], B1l[4];
            #pragma unroll
            for (int tt = 0; tt < 4; tt++) {
                uint32_t wb = ((wn*4+tt)*8 + lr)*36 + s*8 + lc;
                B0h[tt] = sm[uh+wb]; B1h[tt] = sm[uh+wb+4];
                B0l[tt] = sm[ul+wb]; B1l[tt] = sm[ul+wb+4];
            }
            #pragma unroll
            for (int tt = 0; tt < 4; tt++)
                #pragma unroll
                for (int i = 0; i < 2; i++) bmma(d[tt][i], Ah[i], B0h[tt], B1h[tt]);
            #pragma unroll
            for (int tt = 0; tt < 4; tt++)
                #pragma unroll
                for (int i = 0; i < 2; i++) bmma(d[tt][i], Ah[i], B0l[tt], B1l[tt]);
            #pragma unroll
            for (int tt = 0; tt < 4; tt++)
                #pragma unroll
                for (int i = 0; i < 2; i++) bmma(d[tt][i], Al[i], B0h[tt], B1h[tt]);
        }
        // store + reset accumulators
        #pragma unroll
        for (int tt = 0; tt < 4; tt++)
            #pragma unroll
            for (int i = 0; i < 2; i++) {
                size_t o = (size_t)(row0 + (wm*2+i)*16 + lr)*4096 + ch*128 + (wn*4+tt)*8 + lc*2;
                *(float2*)&out[o]          = make_float2(d[tt][i][0], d[tt][i][1]);
                *(float2*)&out[o + 8*4096] = make_float2(d[tt][i][2], d[tt][i][3]);
                d[tt][i][0]=d[tt][i][1]=d[tt][i][2]=d[tt][i][3]=0.f;
            }
    }
}

extern "C" void kernel_launch(void* const* d_in, const int* in_sizes, int n_in,
                              void* d_out, int out_size)
{
    const float*     x  = (const float*)d_in[0];      // [16384,4096]
    const float*     dw = (const float*)d_in[1];      // [64,4096]
    const float*     uw = (const float*)d_in[2];      // [4096,64]
    const float*     tv = (const float*)d_in[3];      // [16384,8]
    const long long* ti = (const long long*)d_in[4];  // [16384,8] i32/i64

    cudaFuncSetAttribute(moe_mma, cudaFuncAttributeMaxDynamicSharedMemorySize, SMEM_SZ);
    kprep<<<2048, 256>>>(dw, uw);
    moe_mma<<<NCTA, THR, SMEM_SZ>>>(x, tv, ti, (float*)d_out);
}